// round 1
// baseline (speedup 1.0000x reference)
#include <cuda_runtime.h>
#include <cuda_bf16.h>

#define BB 64
#define NN 2048
#define DD 1024
#define SPLIT 8
#define RPB 256      // rows per block in k1 = NN/SPLIT
#define ESPLIT 4

// Scratch (static device globals; no allocation)
__device__ float g_scores[BB * NN];            // raw scores
__device__ float g_part_m[BB * SPLIT];
__device__ float g_part_l[BB * SPLIT];
__device__ float g_part_mix[BB * SPLIT * DD];  // un-normalized partial mix
__device__ float g_comb[BB * 2 * DD];          // [mix | output]
__device__ float g_out_part[ESPLIT * BB * DD]; // GEMM e-split partials

// ---------------------------------------------------------------------------
// Kernel 1: fused scores + online softmax + mix accumulation (single ctx pass)
// grid (SPLIT, BB), 256 threads (8 warps). Warp w handles rows w, w+8, ...
// ---------------------------------------------------------------------------
__global__ __launch_bounds__(256, 2)
void k1_scores_mix(const float* __restrict__ output,
                   const float* __restrict__ context) {
    const int split = blockIdx.x;
    const int b     = blockIdx.y;
    const int tid   = threadIdx.x;
    const int w     = tid >> 5;
    const int lane  = tid & 31;

    const float* q   = output + (size_t)b * DD;
    const float* ctx = context + (size_t)b * NN * DD + (size_t)split * RPB * DD;

    // Query in registers: lane covers columns {j*128 + lane*4 .. +3}, j=0..7
    float4 qv[8];
#pragma unroll
    for (int j = 0; j < 8; j++)
        qv[j] = *(const float4*)(q + j * 128 + lane * 4);

    float acc[32];
#pragma unroll
    for (int k = 0; k < 32; k++) acc[k] = 0.f;
    float m = -1e30f, l = 0.f;

    __shared__ float sscores[RPB];
    __shared__ float smix[DD];
    __shared__ float sm[8], sl[8];

    for (int i = 0; i < 32; i++) {
        const int nl = w + 8 * i;
        const float* row = ctx + (size_t)nl * DD;
        float4 cv[8];
#pragma unroll
        for (int j = 0; j < 8; j++)
            cv[j] = *(const float4*)(row + j * 128 + lane * 4);

        float s = 0.f;
#pragma unroll
        for (int j = 0; j < 8; j++) {
            s = fmaf(qv[j].x, cv[j].x, s);
            s = fmaf(qv[j].y, cv[j].y, s);
            s = fmaf(qv[j].z, cv[j].z, s);
            s = fmaf(qv[j].w, cv[j].w, s);
        }
#pragma unroll
        for (int off = 16; off; off >>= 1)
            s += __shfl_xor_sync(0xffffffffu, s, off);

        if (lane == 0) sscores[nl] = s;

        const float mn = fmaxf(m, s);
        const float c  = __expf(m - mn);
        const float p  = __expf(s - mn);
        l = l * c + p;
#pragma unroll
        for (int j = 0; j < 8; j++) {
            acc[4 * j + 0] = fmaf(p, cv[j].x, acc[4 * j + 0] * c);
            acc[4 * j + 1] = fmaf(p, cv[j].y, acc[4 * j + 1] * c);
            acc[4 * j + 2] = fmaf(p, cv[j].z, acc[4 * j + 2] * c);
            acc[4 * j + 3] = fmaf(p, cv[j].w, acc[4 * j + 3] * c);
        }
        m = mn;
    }

    // Block combine: max/sum over 8 warps, rescale mix slices into smem
    for (int d = tid; d < DD; d += 256) smix[d] = 0.f;
    if (lane == 0) { sm[w] = m; sl[w] = l; }
    __syncthreads();

    float M = sm[0];
#pragma unroll
    for (int s2 = 1; s2 < 8; s2++) M = fmaxf(M, sm[s2]);
    float L = 0.f;
#pragma unroll
    for (int s2 = 0; s2 < 8; s2++) L += sl[s2] * __expf(sm[s2] - M);

    const float scale = __expf(m - M);  // m uniform within warp
#pragma unroll
    for (int j = 0; j < 8; j++) {
        atomicAdd(&smix[j * 128 + lane * 4 + 0], acc[4 * j + 0] * scale);
        atomicAdd(&smix[j * 128 + lane * 4 + 1], acc[4 * j + 1] * scale);
        atomicAdd(&smix[j * 128 + lane * 4 + 2], acc[4 * j + 2] * scale);
        atomicAdd(&smix[j * 128 + lane * 4 + 3], acc[4 * j + 3] * scale);
    }
    __syncthreads();

    const int ps = b * SPLIT + split;
    if (tid == 0) { g_part_m[ps] = M; g_part_l[ps] = L; }
    for (int d = tid; d < DD; d += 256)
        g_part_mix[(size_t)ps * DD + d] = smix[d];
    for (int nl = tid; nl < RPB; nl += 256)
        g_scores[(size_t)b * NN + split * RPB + nl] = sscores[nl];
}

// ---------------------------------------------------------------------------
// Kernel 2: combine splits -> final mix; build [mix|output]; write attn
// grid BB, 256 threads
// ---------------------------------------------------------------------------
__global__ void k2_combine(const float* __restrict__ output,
                           float* __restrict__ attn_out) {
    const int b   = blockIdx.x;
    const int tid = threadIdx.x;

    float M = -1e30f;
#pragma unroll
    for (int s = 0; s < SPLIT; s++) M = fmaxf(M, g_part_m[b * SPLIT + s]);
    float wgt[SPLIT];
    float L = 0.f;
#pragma unroll
    for (int s = 0; s < SPLIT; s++) {
        wgt[s] = __expf(g_part_m[b * SPLIT + s] - M);
        L += g_part_l[b * SPLIT + s] * wgt[s];
    }
    const float invL = 1.f / L;

    for (int d = tid; d < DD; d += blockDim.x) {
        float a = 0.f;
#pragma unroll
        for (int s = 0; s < SPLIT; s++)
            a += g_part_mix[(size_t)(b * SPLIT + s) * DD + d] * wgt[s];
        g_comb[(size_t)b * 2 * DD + d] = a * invL;
    }
    for (int d = tid; d < DD; d += blockDim.x)
        g_comb[(size_t)b * 2 * DD + DD + d] = output[(size_t)b * DD + d];
    for (int n = tid; n < NN; n += blockDim.x)
        attn_out[(size_t)b * NN + n] =
            __expf(g_scores[(size_t)b * NN + n] - M) * invL;
}

// ---------------------------------------------------------------------------
// Kernel 3: out_part = comb @ W^T, tiled.  Block: 32 d x 64 b x 512 e.
// grid (32, ESPLIT), 128 threads, 4x4 register tile per thread.
// ---------------------------------------------------------------------------
__global__ __launch_bounds__(128)
void k3_gemm(const float* __restrict__ W) {
    const int dt  = blockIdx.x;       // d tile: 32 d's
    const int es  = blockIdx.y;       // e split: 512 e's
    const int tid = threadIdx.x;
    const int d0  = dt * 32;
    const int e0  = es * 512;
    const int dg  = tid & 7;          // 0..7
    const int bg  = tid >> 3;         // 0..15

    __shared__ float Ws[32][33];
    __shared__ float Cs[64][33];

    float acc[4][4];
#pragma unroll
    for (int i = 0; i < 4; i++)
#pragma unroll
        for (int j = 0; j < 4; j++) acc[i][j] = 0.f;

    for (int ec = 0; ec < 512; ec += 32) {
#pragma unroll
        for (int i = 0; i < 8; i++) {
            int idx = tid + i * 128;
            int r = idx >> 5, c = idx & 31;
            Ws[r][c] = W[(size_t)(d0 + r) * (2 * DD) + e0 + ec + c];
        }
#pragma unroll
        for (int i = 0; i < 16; i++) {
            int idx = tid + i * 128;
            int r = idx >> 5, c = idx & 31;
            Cs[r][c] = g_comb[(size_t)r * (2 * DD) + e0 + ec + c];
        }
        __syncthreads();
#pragma unroll
        for (int k = 0; k < 32; k++) {
            float wv[4], cv[4];
#pragma unroll
            for (int j = 0; j < 4; j++) wv[j] = Ws[dg + 8 * j][k];
#pragma unroll
            for (int i = 0; i < 4; i++) cv[i] = Cs[bg + 16 * i][k];
#pragma unroll
            for (int i = 0; i < 4; i++)
#pragma unroll
                for (int j = 0; j < 4; j++)
                    acc[i][j] = fmaf(cv[i], wv[j], acc[i][j]);
        }
        __syncthreads();
    }

#pragma unroll
    for (int i = 0; i < 4; i++)
#pragma unroll
        for (int j = 0; j < 4; j++) {
            int bidx = bg + 16 * i;
            int didx = d0 + dg + 8 * j;
            g_out_part[(size_t)es * BB * DD + (size_t)bidx * DD + didx] =
                acc[i][j];
        }
}

// ---------------------------------------------------------------------------
// Kernel 4: sum e-split partials + bias, tanh, write out
// ---------------------------------------------------------------------------
__global__ void k4_final(const float* __restrict__ bias,
                         float* __restrict__ out) {
    const int idx = blockIdx.x * blockDim.x + threadIdx.x;  // 0..65535
    const int d = idx & (DD - 1);
    float a = bias[d];
#pragma unroll
    for (int es = 0; es < ESPLIT; es++)
        a += g_out_part[(size_t)es * BB * DD + idx];
    out[idx] = tanhf(a);
}

// ---------------------------------------------------------------------------
extern "C" void kernel_launch(void* const* d_in, const int* in_sizes, int n_in,
                              void* d_out, int out_size) {
    const float* output  = (const float*)d_in[0];  // (64,1,1024)
    const float* context = (const float*)d_in[1];  // (64,2048,1024)
    const float* W_out   = (const float*)d_in[2];  // (1024,2048)
    const float* b_out   = (const float*)d_in[3];  // (1024)

    float* out  = (float*)d_out;          // (64,1,1024) first
    float* attn = out + BB * DD;          // (64,1,2048) second

    k1_scores_mix<<<dim3(SPLIT, BB), 256>>>(output, context);
    k2_combine<<<BB, 256>>>(output, attn);
    k3_gemm<<<dim3(32, ESPLIT), 128>>>(W_out);
    k4_final<<<256, 256>>>(b_out, out);
}